// round 7
// baseline (speedup 1.0000x reference)
#include <cuda_runtime.h>
#include <math.h>
#include <stdint.h>

#define N_NODES 50000
#define E_RAW   400000
#define E_TOT   (E_RAW + N_NODES)   // 450000 with self loops
#define IN_DIM  128
#define H1      4
#define C1      64
#define F1      256                 // H1*C1
#define C2      64
#define OUT_DIM 3
#define NEG_SLOPE 0.2f
#define EPSV    1e-16f
#define NB_SCAN ((N_NODES + 255) / 256)   // 196 scan blocks

// ---------------- scratch (static device globals; no allocation) ----------------
__device__ __align__(16) float g_h1[N_NODES * F1];    // x @ W1
__device__ __align__(16) float g_out1[N_NODES * F1];  // elu(agg1 + b1) -> layer-2 input
__device__ __align__(16) float g_as1[N_NODES * H1];
__device__ __align__(16) float g_ad1[N_NODES * H1];
__device__ __align__(16) float g_e1[E_TOT * H1];      // exp scores, CSR order

__device__ __align__(16) float g_h2[N_NODES * C2];    // layer-2 linear
__device__ float g_as2[N_NODES];
__device__ float g_ad2[N_NODES];
__device__ float g_e2[E_TOT];                          // exp scores, CSR order

__device__ int g_cnt[N_NODES];       // in-degree (incl self loop)
__device__ int g_row[N_NODES];       // CSR row start
__device__ int g_fill[N_NODES];
__device__ int g_bsum[NB_SCAN];
__device__ int g_csr_src[E_TOT];     // src node per CSR slot
__device__ int g_is64;

// ---------------- helpers ----------------
__device__ __forceinline__ float eluf(float x) {
    return x > 0.f ? x : expm1f(x);
}

__device__ __forceinline__ void load_edge(const void* ei, int e, int& s, int& d) {
    if (e >= E_RAW) { s = d = e - E_RAW; return; }
    if (g_is64) {
        const long long* p = (const long long*)ei;
        s = (int)p[e];
        d = (int)p[E_RAW + e];
    } else {
        const int* p = (const int*)ei;
        s = p[e];
        d = p[E_RAW + e];
    }
}

// ---------------- edge index dtype detect ----------------
__global__ void detect_kernel(const unsigned int* __restrict__ ei32) {
    if (threadIdx.x == 0 && blockIdx.x == 0) {
        unsigned int ornz = 0;
        #pragma unroll
        for (int i = 0; i < 64; i++) ornz |= ei32[2 * i + 1];
        g_is64 = (ornz == 0u) ? 1 : 0;
    }
}

// ---------------- CSR build ----------------
__global__ void zero_kernel() {
    int n = blockIdx.x * blockDim.x + threadIdx.x;
    if (n < N_NODES) { g_cnt[n] = 0; g_fill[n] = 0; }
}

__global__ void count_kernel(const void* __restrict__ ei) {
    int e = blockIdx.x * blockDim.x + threadIdx.x;
    if (e >= E_TOT) return;
    int s, d; load_edge(ei, e, s, d);
    atomicAdd(&g_cnt[d], 1);
}

__global__ void scan1_kernel() {
    __shared__ int sm[256];
    int tid = threadIdx.x;
    int gid = blockIdx.x * 256 + tid;
    int v = (gid < N_NODES) ? g_cnt[gid] : 0;
    sm[tid] = v;
    __syncthreads();
    #pragma unroll
    for (int off = 1; off < 256; off <<= 1) {
        int t = (tid >= off) ? sm[tid - off] : 0;
        __syncthreads();
        sm[tid] += t;
        __syncthreads();
    }
    if (gid < N_NODES) g_row[gid] = sm[tid] - v;
    if (tid == 255) g_bsum[blockIdx.x] = sm[255];
}

// fused: each block computes its global offset from block sums, applies it
__global__ void scan23_kernel() {
    __shared__ int sred[256];
    int tid = threadIdx.x, bid = blockIdx.x;
    int v = 0;
    for (int i = tid; i < bid; i += 256) v += g_bsum[i];
    sred[tid] = v;
    __syncthreads();
    #pragma unroll
    for (int o = 128; o; o >>= 1) {
        if (tid < o) sred[tid] += sred[tid + o];
        __syncthreads();
    }
    int off = sred[0];
    int gid = bid * 256 + tid;
    if (gid < N_NODES) g_row[gid] += off;
}

__global__ void scatter_kernel(const void* __restrict__ ei) {
    int e = blockIdx.x * blockDim.x + threadIdx.x;
    if (e >= E_TOT) return;
    int s, d; load_edge(ei, e, s, d);
    int pos = g_row[d] + atomicAdd(&g_fill[d], 1);
    g_csr_src[pos] = s;
}

// ---------------- GEMM + fused attention scores (register double-buffered) -------
// C[M,N] = A[M,K] @ B[K,N]; as_out[row,h] = sum_c C[row,h*64+c]*att_src[h*64+c]
// BM=128, BK=16, 256 threads (16x16), microtile 8 x TN. NH = BN/64 heads per block.
template<int BN, int TN, int NH>
__global__ __launch_bounds__(256, 2) void gemm_att_kernel(
    const float* __restrict__ A, const float* __restrict__ B, float* __restrict__ C,
    const float* __restrict__ att_src, const float* __restrict__ att_dst,
    float* __restrict__ as_out, float* __restrict__ ad_out,
    int M, int K, int N, int HTOT)
{
    constexpr int NBL = BN / 64;       // B-tile float4 loads per thread
    __shared__ float As[16][128];
    __shared__ float Bs[16][BN];
    const int tid = threadIdx.x;
    const int tx = tid & 15;
    const int ty = tid >> 4;
    const int by = blockIdx.y * 128, bx = blockIdx.x * BN;

    // A-load decode (constant per thread)
    const int ar0 = tid >> 2, ac0 = (tid & 3) * 4;
    const int ar1 = (tid + 256) >> 2, ac1 = ((tid + 256) & 3) * 4;
    const int arow0 = by + ar0, arow1 = by + ar1;

    float acc[8][TN];
    #pragma unroll
    for (int m = 0; m < 8; m++)
        #pragma unroll
        for (int n = 0; n < TN; n++) acc[m][n] = 0.f;

    float4 rA0, rA1, rB[NBL];
    // prefetch tile 0
    rA0 = (arow0 < M) ? *(const float4*)&A[(long)arow0 * K + ac0] : make_float4(0,0,0,0);
    rA1 = (arow1 < M) ? *(const float4*)&A[(long)arow1 * K + ac1] : make_float4(0,0,0,0);
    #pragma unroll
    for (int i = 0; i < NBL; i++) {
        int idx = tid + i * 256;
        int r = idx / (BN / 4), c4 = (idx % (BN / 4)) * 4;
        rB[i] = *(const float4*)&B[(long)r * N + bx + c4];
    }

    for (int k0 = 0; k0 < K; k0 += 16) {
        // commit prefetched regs to smem
        As[ac0 + 0][ar0] = rA0.x; As[ac0 + 1][ar0] = rA0.y;
        As[ac0 + 2][ar0] = rA0.z; As[ac0 + 3][ar0] = rA0.w;
        As[ac1 + 0][ar1] = rA1.x; As[ac1 + 1][ar1] = rA1.y;
        As[ac1 + 2][ar1] = rA1.z; As[ac1 + 3][ar1] = rA1.w;
        #pragma unroll
        for (int i = 0; i < NBL; i++) {
            int idx = tid + i * 256;
            int r = idx / (BN / 4), c4 = (idx % (BN / 4)) * 4;
            *(float4*)&Bs[r][c4] = rB[i];
        }
        __syncthreads();
        // prefetch next tile
        int kn = k0 + 16;
        if (kn < K) {
            rA0 = (arow0 < M) ? *(const float4*)&A[(long)arow0 * K + kn + ac0] : make_float4(0,0,0,0);
            rA1 = (arow1 < M) ? *(const float4*)&A[(long)arow1 * K + kn + ac1] : make_float4(0,0,0,0);
            #pragma unroll
            for (int i = 0; i < NBL; i++) {
                int idx = tid + i * 256;
                int r = idx / (BN / 4), c4 = (idx % (BN / 4)) * 4;
                rB[i] = *(const float4*)&B[(long)(kn + r) * N + bx + c4];
            }
        }
        // compute
        #pragma unroll
        for (int kk = 0; kk < 16; kk++) {
            float a[8], b[TN];
            #pragma unroll
            for (int m = 0; m < 8; m++) a[m] = As[kk][ty * 8 + m];
            #pragma unroll
            for (int n = 0; n < TN; n++) b[n] = Bs[kk][tx * TN + n];
            #pragma unroll
            for (int m = 0; m < 8; m++)
                #pragma unroll
                for (int n = 0; n < TN; n++)
                    acc[m][n] = fmaf(a[m], b[n], acc[m][n]);
        }
        __syncthreads();
    }

    // store C
    #pragma unroll
    for (int m = 0; m < 8; m++) {
        int row = by + ty * 8 + m;
        if (row < M) {
            #pragma unroll
            for (int n4 = 0; n4 < TN / 4; n4++) {
                float4 v = make_float4(acc[m][n4 * 4 + 0], acc[m][n4 * 4 + 1],
                                       acc[m][n4 * 4 + 2], acc[m][n4 * 4 + 3]);
                *(float4*)&C[(long)row * N + bx + tx * TN + n4 * 4] = v;
            }
        }
    }

    // fused attention partials
    float att_s[TN], att_d[TN];
    #pragma unroll
    for (int n = 0; n < TN; n++) {
        int col = bx + tx * TN + n;
        att_s[n] = att_src[col];
        att_d[n] = att_dst[col];
    }
    #pragma unroll
    for (int m = 0; m < 8; m++) {
        float s = 0.f, d = 0.f;
        #pragma unroll
        for (int n = 0; n < TN; n++) {
            s = fmaf(acc[m][n], att_s[n], s);
            d = fmaf(acc[m][n], att_d[n], d);
        }
        #pragma unroll
        for (int o = 4; o; o >>= 1) {
            s += __shfl_down_sync(0xffffffffu, s, o, 8);
            d += __shfl_down_sync(0xffffffffu, d, o, 8);
        }
        if (NH == 1) {
            s += __shfl_down_sync(0xffffffffu, s, 8, 16);
            d += __shfl_down_sync(0xffffffffu, d, 8, 16);
            if (tx == 0) {
                int row = by + ty * 8 + m;
                if (row < M) {
                    int head = bx / 64;
                    as_out[row * HTOT + head] = s;
                    ad_out[row * HTOT + head] = d;
                }
            }
        } else {
            if ((tx & 7) == 0) {
                int row = by + ty * 8 + m;
                if (row < M) {
                    int head = (bx + tx * TN) / 64;
                    as_out[row * HTOT + head] = s;
                    ad_out[row * HTOT + head] = d;
                }
            }
        }
    }
}

// ---------------- layer 1: fused softmax + aggregation + bias + elu ----------------
// one warp per dst node; lane owns cols [lane*8, lane*8+8); gather loop unrolled x4
__global__ __launch_bounds__(256) void agg1_kernel(const float* __restrict__ b1) {
    int w = (blockIdx.x * blockDim.x + threadIdx.x) >> 5;
    int lane = threadIdx.x & 31;
    if (w >= N_NODES) return;
    int start = g_row[w];
    int end = start + g_cnt[w];

    float4 ad = *(const float4*)&g_ad1[w * H1];
    float4 den = make_float4(0.f, 0.f, 0.f, 0.f);
    for (int i = start + lane; i < end; i += 32) {
        int s = g_csr_src[i];
        float4 as = *(const float4*)&g_as1[s * H1];
        float4 v;
        v.x = as.x + ad.x; v.y = as.y + ad.y; v.z = as.z + ad.z; v.w = as.w + ad.w;
        v.x = __expf(v.x > 0.f ? v.x : NEG_SLOPE * v.x);
        v.y = __expf(v.y > 0.f ? v.y : NEG_SLOPE * v.y);
        v.z = __expf(v.z > 0.f ? v.z : NEG_SLOPE * v.z);
        v.w = __expf(v.w > 0.f ? v.w : NEG_SLOPE * v.w);
        *(float4*)&g_e1[(long)i * H1] = v;
        den.x += v.x; den.y += v.y; den.z += v.z; den.w += v.w;
    }
    #pragma unroll
    for (int o = 16; o; o >>= 1) {
        den.x += __shfl_xor_sync(0xffffffffu, den.x, o);
        den.y += __shfl_xor_sync(0xffffffffu, den.y, o);
        den.z += __shfl_xor_sync(0xffffffffu, den.z, o);
        den.w += __shfl_xor_sync(0xffffffffu, den.w, o);
    }
    int h = lane >> 3;
    float denh = (h == 0) ? den.x : (h == 1) ? den.y : (h == 2) ? den.z : den.w;
    float inv = 1.f / (denh + EPSV);

    float4 acc0 = make_float4(0.f, 0.f, 0.f, 0.f);
    float4 acc1 = make_float4(0.f, 0.f, 0.f, 0.f);
    const int cb = lane * 8;
    int i = start;
    for (; i + 4 <= end; i += 4) {
        int s0 = g_csr_src[i],     s1 = g_csr_src[i + 1];
        int s2 = g_csr_src[i + 2], s3 = g_csr_src[i + 3];
        float4 e0 = *(const float4*)&g_e1[(long)(i    ) * H1];
        float4 e1 = *(const float4*)&g_e1[(long)(i + 1) * H1];
        float4 e2 = *(const float4*)&g_e1[(long)(i + 2) * H1];
        float4 e3 = *(const float4*)&g_e1[(long)(i + 3) * H1];
        const float4* p0 = (const float4*)&g_h1[(long)s0 * F1 + cb];
        const float4* p1 = (const float4*)&g_h1[(long)s1 * F1 + cb];
        const float4* p2 = (const float4*)&g_h1[(long)s2 * F1 + cb];
        const float4* p3 = (const float4*)&g_h1[(long)s3 * F1 + cb];
        float4 x00 = p0[0], x01 = p0[1];
        float4 x10 = p1[0], x11 = p1[1];
        float4 x20 = p2[0], x21 = p2[1];
        float4 x30 = p3[0], x31 = p3[1];
        float a0 = ((h == 0) ? e0.x : (h == 1) ? e0.y : (h == 2) ? e0.z : e0.w) * inv;
        float a1 = ((h == 0) ? e1.x : (h == 1) ? e1.y : (h == 2) ? e1.z : e1.w) * inv;
        float a2 = ((h == 0) ? e2.x : (h == 1) ? e2.y : (h == 2) ? e2.z : e2.w) * inv;
        float a3 = ((h == 0) ? e3.x : (h == 1) ? e3.y : (h == 2) ? e3.z : e3.w) * inv;
        acc0.x = fmaf(a0, x00.x, acc0.x); acc0.y = fmaf(a0, x00.y, acc0.y);
        acc0.z = fmaf(a0, x00.z, acc0.z); acc0.w = fmaf(a0, x00.w, acc0.w);
        acc1.x = fmaf(a0, x01.x, acc1.x); acc1.y = fmaf(a0, x01.y, acc1.y);
        acc1.z = fmaf(a0, x01.z, acc1.z); acc1.w = fmaf(a0, x01.w, acc1.w);
        acc0.x = fmaf(a1, x10.x, acc0.x); acc0.y = fmaf(a1, x10.y, acc0.y);
        acc0.z = fmaf(a1, x10.z, acc0.z); acc0.w = fmaf(a1, x10.w, acc0.w);
        acc1.x = fmaf(a1, x11.x, acc1.x); acc1.y = fmaf(a1, x11.y, acc1.y);
        acc1.z = fmaf(a1, x11.z, acc1.z); acc1.w = fmaf(a1, x11.w, acc1.w);
        acc0.x = fmaf(a2, x20.x, acc0.x); acc0.y = fmaf(a2, x20.y, acc0.y);
        acc0.z = fmaf(a2, x20.z, acc0.z); acc0.w = fmaf(a2, x20.w, acc0.w);
        acc1.x = fmaf(a2, x21.x, acc1.x); acc1.y = fmaf(a2, x21.y, acc1.y);
        acc1.z = fmaf(a2, x21.z, acc1.z); acc1.w = fmaf(a2, x21.w, acc1.w);
        acc0.x = fmaf(a3, x30.x, acc0.x); acc0.y = fmaf(a3, x30.y, acc0.y);
        acc0.z = fmaf(a3, x30.z, acc0.z); acc0.w = fmaf(a3, x30.w, acc0.w);
        acc1.x = fmaf(a3, x31.x, acc1.x); acc1.y = fmaf(a3, x31.y, acc1.y);
        acc1.z = fmaf(a3, x31.z, acc1.z); acc1.w = fmaf(a3, x31.w, acc1.w);
    }
    for (; i < end; i++) {
        int s0 = g_csr_src[i];
        float4 e0 = *(const float4*)&g_e1[(long)i * H1];
        float a0 = ((h == 0) ? e0.x : (h == 1) ? e0.y : (h == 2) ? e0.z : e0.w) * inv;
        const float4* p0 = (const float4*)&g_h1[(long)s0 * F1 + cb];
        float4 x00 = p0[0], x01 = p0[1];
        acc0.x = fmaf(a0, x00.x, acc0.x); acc0.y = fmaf(a0, x00.y, acc0.y);
        acc0.z = fmaf(a0, x00.z, acc0.z); acc0.w = fmaf(a0, x00.w, acc0.w);
        acc1.x = fmaf(a0, x01.x, acc1.x); acc1.y = fmaf(a0, x01.y, acc1.y);
        acc1.z = fmaf(a0, x01.z, acc1.z); acc1.w = fmaf(a0, x01.w, acc1.w);
    }
    float4 bb0 = *(const float4*)&b1[cb];
    float4 bb1 = *(const float4*)&b1[cb + 4];
    acc0.x = eluf(acc0.x + bb0.x); acc0.y = eluf(acc0.y + bb0.y);
    acc0.z = eluf(acc0.z + bb0.z); acc0.w = eluf(acc0.w + bb0.w);
    acc1.x = eluf(acc1.x + bb1.x); acc1.y = eluf(acc1.y + bb1.y);
    acc1.z = eluf(acc1.z + bb1.z); acc1.w = eluf(acc1.w + bb1.w);
    float4* op = (float4*)&g_out1[(long)w * F1 + cb];
    op[0] = acc0;
    op[1] = acc1;
}

// ---------------- layer 2: fused softmax + aggregation + bias + elu + head ----------
__global__ __launch_bounds__(256) void agg2_kernel(const float* __restrict__ b2,
                                                   const float* __restrict__ Wout,
                                                   const float* __restrict__ bout,
                                                   float* __restrict__ out) {
    int w = (blockIdx.x * blockDim.x + threadIdx.x) >> 5;
    int lane = threadIdx.x & 31;
    if (w >= N_NODES) return;
    int start = g_row[w];
    int end = start + g_cnt[w];

    float ad = g_ad2[w];
    float den = 0.f;
    for (int i = start + lane; i < end; i += 32) {
        int s = g_csr_src[i];
        float v = g_as2[s] + ad;
        v = v > 0.f ? v : NEG_SLOPE * v;
        float ex = __expf(v);
        g_e2[i] = ex;
        den += ex;
    }
    #pragma unroll
    for (int o = 16; o; o >>= 1) den += __shfl_xor_sync(0xffffffffu, den, o);
    float inv = 1.f / (den + EPSV);

    int c0 = lane * 2;
    float acc0 = 0.f, acc1 = 0.f;
    int i = start;
    for (; i + 4 <= end; i += 4) {
        int s0 = g_csr_src[i],     s1 = g_csr_src[i + 1];
        int s2 = g_csr_src[i + 2], s3 = g_csr_src[i + 3];
        float a0 = g_e2[i] * inv,     a1 = g_e2[i + 1] * inv;
        float a2 = g_e2[i + 2] * inv, a3 = g_e2[i + 3] * inv;
        float2 h0 = *(const float2*)&g_h2[(long)s0 * C2 + c0];
        float2 h1 = *(const float2*)&g_h2[(long)s1 * C2 + c0];
        float2 h2 = *(const float2*)&g_h2[(long)s2 * C2 + c0];
        float2 h3 = *(const float2*)&g_h2[(long)s3 * C2 + c0];
        acc0 = fmaf(a0, h0.x, acc0); acc1 = fmaf(a0, h0.y, acc1);
        acc0 = fmaf(a1, h1.x, acc0); acc1 = fmaf(a1, h1.y, acc1);
        acc0 = fmaf(a2, h2.x, acc0); acc1 = fmaf(a2, h2.y, acc1);
        acc0 = fmaf(a3, h3.x, acc0); acc1 = fmaf(a3, h3.y, acc1);
    }
    for (; i < end; i++) {
        int s0 = g_csr_src[i];
        float a0 = g_e2[i] * inv;
        float2 h0 = *(const float2*)&g_h2[(long)s0 * C2 + c0];
        acc0 = fmaf(a0, h0.x, acc0); acc1 = fmaf(a0, h0.y, acc1);
    }
    float v0 = eluf(acc0 + b2[c0]);
    float v1 = eluf(acc1 + b2[c0 + 1]);
    float p0 = fmaf(v0, Wout[c0 * 3 + 0], v1 * Wout[(c0 + 1) * 3 + 0]);
    float p1 = fmaf(v0, Wout[c0 * 3 + 1], v1 * Wout[(c0 + 1) * 3 + 1]);
    float p2 = fmaf(v0, Wout[c0 * 3 + 2], v1 * Wout[(c0 + 1) * 3 + 2]);
    #pragma unroll
    for (int o = 16; o; o >>= 1) {
        p0 += __shfl_xor_sync(0xffffffffu, p0, o);
        p1 += __shfl_xor_sync(0xffffffffu, p1, o);
        p2 += __shfl_xor_sync(0xffffffffu, p2, o);
    }
    if (lane == 0) {
        out[w * 3 + 0] = p0 + bout[0];
        out[w * 3 + 1] = p1 + bout[1];
        out[w * 3 + 2] = p2 + bout[2];
    }
}

// ---------------- launch ----------------
extern "C" void kernel_launch(void* const* d_in, const int* in_sizes, int n_in,
                              void* d_out, int out_size) {
    const float* x        = (const float*)d_in[0];
    const void*  ei       = d_in[1];
    const float* W1       = (const float*)d_in[2];
    const float* att_src1 = (const float*)d_in[3];
    const float* att_dst1 = (const float*)d_in[4];
    const float* b1       = (const float*)d_in[5];
    const float* W2       = (const float*)d_in[6];
    const float* att_src2 = (const float*)d_in[7];
    const float* att_dst2 = (const float*)d_in[8];
    const float* b2       = (const float*)d_in[9];
    const float* Wout     = (const float*)d_in[10];
    const float* bout     = (const float*)d_in[11];
    float* out = (float*)d_out;

    float *p_h1, *p_out1, *p_h2, *p_as1, *p_ad1, *p_as2, *p_ad2;
    cudaGetSymbolAddress((void**)&p_h1,   g_h1);
    cudaGetSymbolAddress((void**)&p_out1, g_out1);
    cudaGetSymbolAddress((void**)&p_h2,   g_h2);
    cudaGetSymbolAddress((void**)&p_as1,  g_as1);
    cudaGetSymbolAddress((void**)&p_ad1,  g_ad1);
    cudaGetSymbolAddress((void**)&p_as2,  g_as2);
    cudaGetSymbolAddress((void**)&p_ad2,  g_ad2);

    const int T = 256;
    const int EB = (E_TOT + T - 1) / T;

    // CSR build
    detect_kernel<<<1, 32>>>((const unsigned int*)ei);
    zero_kernel<<<NB_SCAN, T>>>();
    count_kernel<<<EB, T>>>(ei);
    scan1_kernel<<<NB_SCAN, 256>>>();
    scan23_kernel<<<NB_SCAN, 256>>>();
    scatter_kernel<<<EB, T>>>(ei);

    // layer 1: GEMM (+fused attscore), then aggregation
    {
        dim3 grid(F1 / 128, (N_NODES + 127) / 128);
        gemm_att_kernel<128, 8, 2><<<grid, 256>>>(x, W1, p_h1, att_src1, att_dst1,
                                                  p_as1, p_ad1, N_NODES, IN_DIM, F1, H1);
    }
    agg1_kernel<<<(N_NODES * 32 + T - 1) / T, T>>>(b1);

    // layer 2
    {
        dim3 grid(C2 / 64, (N_NODES + 127) / 128);
        gemm_att_kernel<64, 4, 1><<<grid, 256>>>(p_out1, W2, p_h2, att_src2, att_dst2,
                                                 p_as2, p_ad2, N_NODES, F1, C2, 1);
    }
    agg2_kernel<<<(N_NODES * 32 + T - 1) / T, T>>>(b2, Wout, bout, out);
}

// round 8
// speedup vs baseline: 1.1701x; 1.1701x over previous
#include <cuda_runtime.h>
#include <cuda_fp16.h>
#include <math.h>
#include <stdint.h>

#define N_NODES 50000
#define E_RAW   400000
#define E_TOT   (E_RAW + N_NODES)   // 450000 with self loops
#define IN_DIM  128
#define H1      4
#define C1      64
#define F1      256                 // H1*C1
#define C2      64
#define OUT_DIM 3
#define NEG_SLOPE 0.2f
#define EPSV    1e-16f
#define NB_SCAN ((N_NODES + 255) / 256)   // 196 scan blocks

// ---------------- scratch (static device globals; no allocation) ----------------
__device__ __align__(16) __half g_h1h[N_NODES * F1];  // x @ W1 (fp16, gather only)
__device__ __align__(16) float  g_out1[N_NODES * F1]; // elu(agg1 + b1) -> layer-2 input
__device__ __align__(16) float  g_as1[N_NODES * H1];
__device__ __align__(16) float  g_ad1[N_NODES * H1];
__device__ __align__(16) float  g_e1[E_TOT * H1];     // exp scores, CSR order

__device__ __align__(16) __half g_h2h[N_NODES * C2];  // layer-2 linear (fp16, gather only)
__device__ float g_as2[N_NODES];
__device__ float g_ad2[N_NODES];
__device__ float g_e2[E_TOT];                          // exp scores, CSR order

__device__ int g_cnt[N_NODES];       // in-degree (incl self loop)
__device__ int g_row[N_NODES];       // CSR row start
__device__ int g_fill[N_NODES];
__device__ int g_bsum[NB_SCAN];
__device__ int g_csr_src[E_TOT];     // src node per CSR slot
__device__ int g_is64;

// ---------------- helpers ----------------
__device__ __forceinline__ float eluf(float x) {
    return x > 0.f ? x : expm1f(x);
}

__device__ __forceinline__ void load_edge(const void* ei, int e, int& s, int& d) {
    if (e >= E_RAW) { s = d = e - E_RAW; return; }
    if (g_is64) {
        const long long* p = (const long long*)ei;
        s = (int)p[e];
        d = (int)p[E_RAW + e];
    } else {
        const int* p = (const int*)ei;
        s = p[e];
        d = p[E_RAW + e];
    }
}

// ---------------- edge index dtype detect ----------------
__global__ void detect_kernel(const unsigned int* __restrict__ ei32) {
    if (threadIdx.x == 0 && blockIdx.x == 0) {
        unsigned int ornz = 0;
        #pragma unroll
        for (int i = 0; i < 64; i++) ornz |= ei32[2 * i + 1];
        g_is64 = (ornz == 0u) ? 1 : 0;
    }
}

// ---------------- CSR build ----------------
__global__ void zero_kernel() {
    int n = blockIdx.x * blockDim.x + threadIdx.x;
    if (n < N_NODES) { g_cnt[n] = 0; g_fill[n] = 0; }
}

__global__ void count_kernel(const void* __restrict__ ei) {
    int e = blockIdx.x * blockDim.x + threadIdx.x;
    if (e >= E_TOT) return;
    int s, d; load_edge(ei, e, s, d);
    atomicAdd(&g_cnt[d], 1);
}

__global__ void scan1_kernel() {
    __shared__ int sm[256];
    int tid = threadIdx.x;
    int gid = blockIdx.x * 256 + tid;
    int v = (gid < N_NODES) ? g_cnt[gid] : 0;
    sm[tid] = v;
    __syncthreads();
    #pragma unroll
    for (int off = 1; off < 256; off <<= 1) {
        int t = (tid >= off) ? sm[tid - off] : 0;
        __syncthreads();
        sm[tid] += t;
        __syncthreads();
    }
    if (gid < N_NODES) g_row[gid] = sm[tid] - v;
    if (tid == 255) g_bsum[blockIdx.x] = sm[255];
}

// fused: each block computes its global offset from predecessor block sums, applies it
__global__ void scan23_kernel() {
    __shared__ int sred[256];
    int tid = threadIdx.x, bid = blockIdx.x;
    int v = 0;
    for (int i = tid; i < bid; i += 256) v += g_bsum[i];
    sred[tid] = v;
    __syncthreads();
    #pragma unroll
    for (int o = 128; o; o >>= 1) {
        if (tid < o) sred[tid] += sred[tid + o];
        __syncthreads();
    }
    int off = sred[0];
    int gid = bid * 256 + tid;
    if (gid < N_NODES) g_row[gid] += off;
}

__global__ void scatter_kernel(const void* __restrict__ ei) {
    int e = blockIdx.x * blockDim.x + threadIdx.x;
    if (e >= E_TOT) return;
    int s, d; load_edge(ei, e, s, d);
    int pos = g_row[d] + atomicAdd(&g_fill[d], 1);
    g_csr_src[pos] = s;
}

// ---------------- GEMM + fused attention scores, half output -------
// C[M,N] = A[M,K] @ B[K,N] (stored fp16); as_out[row,h] = sum_c C[row,h*64+c]*att[h*64+c]
// BM=128, BK=16, 256 threads (16x16), microtile 8 x TN. NH = BN/64 heads per block.
template<int BN, int TN, int NH>
__global__ __launch_bounds__(256, 2) void gemm_att_kernel(
    const float* __restrict__ A, const float* __restrict__ B, __half* __restrict__ C,
    const float* __restrict__ att_src, const float* __restrict__ att_dst,
    float* __restrict__ as_out, float* __restrict__ ad_out,
    int M, int K, int N, int HTOT)
{
    __shared__ float As[16][128];
    __shared__ float Bs[16][BN];
    const int tid = threadIdx.x;
    const int tx = tid & 15;
    const int ty = tid >> 4;
    const int by = blockIdx.y * 128, bx = blockIdx.x * BN;

    float acc[8][TN];
    #pragma unroll
    for (int m = 0; m < 8; m++)
        #pragma unroll
        for (int n = 0; n < TN; n++) acc[m][n] = 0.f;

    for (int k0 = 0; k0 < K; k0 += 16) {
        // A tile: 128x16 = 512 float4, 2 per thread (transposed store)
        #pragma unroll
        for (int i = 0; i < 2; i++) {
            int idx = tid + i * 256;
            int r = idx >> 2, c4 = (idx & 3) * 4;
            int row = by + r;
            float4 v = make_float4(0.f, 0.f, 0.f, 0.f);
            if (row < M) v = *(const float4*)&A[(long)row * K + k0 + c4];
            As[c4 + 0][r] = v.x;
            As[c4 + 1][r] = v.y;
            As[c4 + 2][r] = v.z;
            As[c4 + 3][r] = v.w;
        }
        // B tile: 16 x BN = 4*BN float4, BN/64 per thread
        #pragma unroll
        for (int i = 0; i < BN / 64; i++) {
            int idx = tid + i * 256;
            int r = idx / (BN / 4), c4 = (idx % (BN / 4)) * 4;
            *(float4*)&Bs[r][c4] = *(const float4*)&B[(long)(k0 + r) * N + bx + c4];
        }
        __syncthreads();
        #pragma unroll
        for (int kk = 0; kk < 16; kk++) {
            float a[8], b[TN];
            #pragma unroll
            for (int m = 0; m < 8; m++) a[m] = As[kk][ty * 8 + m];
            #pragma unroll
            for (int n = 0; n < TN; n++) b[n] = Bs[kk][tx * TN + n];
            #pragma unroll
            for (int m = 0; m < 8; m++)
                #pragma unroll
                for (int n = 0; n < TN; n++)
                    acc[m][n] = fmaf(a[m], b[n], acc[m][n]);
        }
        __syncthreads();
    }

    // store C as fp16
    #pragma unroll
    for (int m = 0; m < 8; m++) {
        int row = by + ty * 8 + m;
        if (row < M) {
            __half2 pk[TN / 2];
            #pragma unroll
            for (int n = 0; n < TN; n += 2)
                pk[n / 2] = __floats2half2_rn(acc[m][n], acc[m][n + 1]);
            if (TN == 8)
                *(uint4*)&C[(long)row * N + bx + tx * TN] = *(uint4*)pk;
            else
                *(uint2*)&C[(long)row * N + bx + tx * TN] = *(uint2*)pk;
        }
    }

    // fused attention partials (fp32 accs; zero-padded rows give zero partials)
    float att_s[TN], att_d[TN];
    #pragma unroll
    for (int n = 0; n < TN; n++) {
        int col = bx + tx * TN + n;
        att_s[n] = att_src[col];
        att_d[n] = att_dst[col];
    }
    #pragma unroll
    for (int m = 0; m < 8; m++) {
        float s = 0.f, d = 0.f;
        #pragma unroll
        for (int n = 0; n < TN; n++) {
            s = fmaf(acc[m][n], att_s[n], s);
            d = fmaf(acc[m][n], att_d[n], d);
        }
        #pragma unroll
        for (int o = 4; o; o >>= 1) {
            s += __shfl_down_sync(0xffffffffu, s, o, 8);
            d += __shfl_down_sync(0xffffffffu, d, o, 8);
        }
        if (NH == 1) {
            s += __shfl_down_sync(0xffffffffu, s, 8, 16);
            d += __shfl_down_sync(0xffffffffu, d, 8, 16);
            if (tx == 0) {
                int row = by + ty * 8 + m;
                if (row < M) {
                    int head = bx / 64;
                    as_out[row * HTOT + head] = s;
                    ad_out[row * HTOT + head] = d;
                }
            }
        } else {
            if ((tx & 7) == 0) {
                int row = by + ty * 8 + m;
                if (row < M) {
                    int head = (bx + tx * TN) / 64;
                    as_out[row * HTOT + head] = s;
                    ad_out[row * HTOT + head] = d;
                }
            }
        }
    }
}

// ---------------- layer 1: fused softmax + aggregation + bias + elu ----------------
// one warp per dst node; lane owns cols [lane*8, lane*8+8) = one 16B half8 per edge
__global__ __launch_bounds__(256) void agg1_kernel(const float* __restrict__ b1) {
    int w = (blockIdx.x * blockDim.x + threadIdx.x) >> 5;
    int lane = threadIdx.x & 31;
    if (w >= N_NODES) return;
    int start = g_row[w];
    int end = start + g_cnt[w];

    float4 ad = *(const float4*)&g_ad1[w * H1];
    float4 den = make_float4(0.f, 0.f, 0.f, 0.f);
    for (int i = start + lane; i < end; i += 32) {
        int s = g_csr_src[i];
        float4 as = *(const float4*)&g_as1[s * H1];
        float4 v;
        v.x = as.x + ad.x; v.y = as.y + ad.y; v.z = as.z + ad.z; v.w = as.w + ad.w;
        v.x = __expf(v.x > 0.f ? v.x : NEG_SLOPE * v.x);
        v.y = __expf(v.y > 0.f ? v.y : NEG_SLOPE * v.y);
        v.z = __expf(v.z > 0.f ? v.z : NEG_SLOPE * v.z);
        v.w = __expf(v.w > 0.f ? v.w : NEG_SLOPE * v.w);
        *(float4*)&g_e1[(long)i * H1] = v;
        den.x += v.x; den.y += v.y; den.z += v.z; den.w += v.w;
    }
    #pragma unroll
    for (int o = 16; o; o >>= 1) {
        den.x += __shfl_xor_sync(0xffffffffu, den.x, o);
        den.y += __shfl_xor_sync(0xffffffffu, den.y, o);
        den.z += __shfl_xor_sync(0xffffffffu, den.z, o);
        den.w += __shfl_xor_sync(0xffffffffu, den.w, o);
    }
    int h = lane >> 3;
    float denh = (h == 0) ? den.x : (h == 1) ? den.y : (h == 2) ? den.z : den.w;
    float inv = 1.f / (denh + EPSV);

    float acc[8] = {};
    const int cb = lane * 8;
    int i = start;
    for (; i + 2 <= end; i += 2) {
        int s0 = g_csr_src[i], s1 = g_csr_src[i + 1];
        float4 e0 = *(const float4*)&g_e1[(long)(i    ) * H1];
        float4 e1 = *(const float4*)&g_e1[(long)(i + 1) * H1];
        uint4 r0 = *(const uint4*)&g_h1h[(long)s0 * F1 + cb];
        uint4 r1 = *(const uint4*)&g_h1h[(long)s1 * F1 + cb];
        float a0 = ((h == 0) ? e0.x : (h == 1) ? e0.y : (h == 2) ? e0.z : e0.w) * inv;
        float a1 = ((h == 0) ? e1.x : (h == 1) ? e1.y : (h == 2) ? e1.z : e1.w) * inv;
        const __half2* q0 = (const __half2*)&r0;
        const __half2* q1 = (const __half2*)&r1;
        #pragma unroll
        for (int j = 0; j < 4; j++) {
            float2 f0 = __half22float2(q0[j]);
            float2 f1 = __half22float2(q1[j]);
            acc[j * 2 + 0] = fmaf(a0, f0.x, acc[j * 2 + 0]);
            acc[j * 2 + 1] = fmaf(a0, f0.y, acc[j * 2 + 1]);
            acc[j * 2 + 0] = fmaf(a1, f1.x, acc[j * 2 + 0]);
            acc[j * 2 + 1] = fmaf(a1, f1.y, acc[j * 2 + 1]);
        }
    }
    if (i < end) {
        int s0 = g_csr_src[i];
        float4 e0 = *(const float4*)&g_e1[(long)i * H1];
        float a0 = ((h == 0) ? e0.x : (h == 1) ? e0.y : (h == 2) ? e0.z : e0.w) * inv;
        uint4 r0 = *(const uint4*)&g_h1h[(long)s0 * F1 + cb];
        const __half2* q0 = (const __half2*)&r0;
        #pragma unroll
        for (int j = 0; j < 4; j++) {
            float2 f0 = __half22float2(q0[j]);
            acc[j * 2 + 0] = fmaf(a0, f0.x, acc[j * 2 + 0]);
            acc[j * 2 + 1] = fmaf(a0, f0.y, acc[j * 2 + 1]);
        }
    }
    float4 bb0 = *(const float4*)&b1[cb];
    float4 bb1 = *(const float4*)&b1[cb + 4];
    float4 o0, o1;
    o0.x = eluf(acc[0] + bb0.x); o0.y = eluf(acc[1] + bb0.y);
    o0.z = eluf(acc[2] + bb0.z); o0.w = eluf(acc[3] + bb0.w);
    o1.x = eluf(acc[4] + bb1.x); o1.y = eluf(acc[5] + bb1.y);
    o1.z = eluf(acc[6] + bb1.z); o1.w = eluf(acc[7] + bb1.w);
    float4* op = (float4*)&g_out1[(long)w * F1 + cb];
    op[0] = o0;
    op[1] = o1;
}

// ---------------- layer 2: fused softmax + aggregation + bias + elu + head ----------
__global__ __launch_bounds__(256) void agg2_kernel(const float* __restrict__ b2,
                                                   const float* __restrict__ Wout,
                                                   const float* __restrict__ bout,
                                                   float* __restrict__ out) {
    int w = (blockIdx.x * blockDim.x + threadIdx.x) >> 5;
    int lane = threadIdx.x & 31;
    if (w >= N_NODES) return;
    int start = g_row[w];
    int end = start + g_cnt[w];

    float ad = g_ad2[w];
    float den = 0.f;
    for (int i = start + lane; i < end; i += 32) {
        int s = g_csr_src[i];
        float v = g_as2[s] + ad;
        v = v > 0.f ? v : NEG_SLOPE * v;
        float ex = __expf(v);
        g_e2[i] = ex;
        den += ex;
    }
    #pragma unroll
    for (int o = 16; o; o >>= 1) den += __shfl_xor_sync(0xffffffffu, den, o);
    float inv = 1.f / (den + EPSV);

    int c0 = lane * 2;
    float acc0 = 0.f, acc1 = 0.f;
    int i = start;
    for (; i + 2 <= end; i += 2) {
        int s0 = g_csr_src[i], s1 = g_csr_src[i + 1];
        float a0 = g_e2[i] * inv, a1 = g_e2[i + 1] * inv;
        __half2 h0 = *(const __half2*)&g_h2h[(long)s0 * C2 + c0];
        __half2 h1 = *(const __half2*)&g_h2h[(long)s1 * C2 + c0];
        float2 f0 = __half22float2(h0);
        float2 f1 = __half22float2(h1);
        acc0 = fmaf(a0, f0.x, acc0); acc1 = fmaf(a0, f0.y, acc1);
        acc0 = fmaf(a1, f1.x, acc0); acc1 = fmaf(a1, f1.y, acc1);
    }
    if (i < end) {
        int s0 = g_csr_src[i];
        float a0 = g_e2[i] * inv;
        __half2 h0 = *(const __half2*)&g_h2h[(long)s0 * C2 + c0];
        float2 f0 = __half22float2(h0);
        acc0 = fmaf(a0, f0.x, acc0); acc1 = fmaf(a0, f0.y, acc1);
    }
    float v0 = eluf(acc0 + b2[c0]);
    float v1 = eluf(acc1 + b2[c0 + 1]);
    float p0 = fmaf(v0, Wout[c0 * 3 + 0], v1 * Wout[(c0 + 1) * 3 + 0]);
    float p1 = fmaf(v0, Wout[c0 * 3 + 1], v1 * Wout[(c0 + 1) * 3 + 1]);
    float p2 = fmaf(v0, Wout[c0 * 3 + 2], v1 * Wout[(c0 + 1) * 3 + 2]);
    #pragma unroll
    for (int o = 16; o; o >>= 1) {
        p0 += __shfl_xor_sync(0xffffffffu, p0, o);
        p1 += __shfl_xor_sync(0xffffffffu, p1, o);
        p2 += __shfl_xor_sync(0xffffffffu, p2, o);
    }
    if (lane == 0) {
        out[w * 3 + 0] = p0 + bout[0];
        out[w * 3 + 1] = p1 + bout[1];
        out[w * 3 + 2] = p2 + bout[2];
    }
}

// ---------------- launch ----------------
extern "C" void kernel_launch(void* const* d_in, const int* in_sizes, int n_in,
                              void* d_out, int out_size) {
    const float* x        = (const float*)d_in[0];
    const void*  ei       = d_in[1];
    const float* W1       = (const float*)d_in[2];
    const float* att_src1 = (const float*)d_in[3];
    const float* att_dst1 = (const float*)d_in[4];
    const float* b1       = (const float*)d_in[5];
    const float* W2       = (const float*)d_in[6];
    const float* att_src2 = (const float*)d_in[7];
    const float* att_dst2 = (const float*)d_in[8];
    const float* b2       = (const float*)d_in[9];
    const float* Wout     = (const float*)d_in[10];
    const float* bout     = (const float*)d_in[11];
    float* out = (float*)d_out;

    __half *p_h1h, *p_h2h;
    float *p_out1, *p_as1, *p_ad1, *p_as2, *p_ad2;
    cudaGetSymbolAddress((void**)&p_h1h,  g_h1h);
    cudaGetSymbolAddress((void**)&p_h2h,  g_h2h);
    cudaGetSymbolAddress((void**)&p_out1, g_out1);
    cudaGetSymbolAddress((void**)&p_as1,  g_as1);
    cudaGetSymbolAddress((void**)&p_ad1,  g_ad1);
    cudaGetSymbolAddress((void**)&p_as2,  g_as2);
    cudaGetSymbolAddress((void**)&p_ad2,  g_ad2);

    const int T = 256;
    const int EB = (E_TOT + T - 1) / T;

    // CSR build
    detect_kernel<<<1, 32>>>((const unsigned int*)ei);
    zero_kernel<<<NB_SCAN, T>>>();
    count_kernel<<<EB, T>>>(ei);
    scan1_kernel<<<NB_SCAN, 256>>>();
    scan23_kernel<<<NB_SCAN, 256>>>();
    scatter_kernel<<<EB, T>>>(ei);

    // layer 1: GEMM (+fused attscore, fp16 C), then aggregation
    {
        dim3 grid(F1 / 128, (N_NODES + 127) / 128);
        gemm_att_kernel<128, 8, 2><<<grid, 256>>>(x, W1, p_h1h, att_src1, att_dst1,
                                                  p_as1, p_ad1, N_NODES, IN_DIM, F1, H1);
    }
    agg1_kernel<<<(N_NODES * 32 + T - 1) / T, T>>>(b1);

    // layer 2
    {
        dim3 grid(C2 / 64, (N_NODES + 127) / 128);
        gemm_att_kernel<64, 4, 1><<<grid, 256>>>(p_out1, W2, p_h2h, att_src2, att_dst2,
                                                 p_as2, p_ad2, N_NODES, F1, C2, 1);
    }
    agg2_kernel<<<(N_NODES * 32 + T - 1) / T, T>>>(b2, Wout, bout, out);
}

// round 9
// speedup vs baseline: 1.1998x; 1.0254x over previous
#include <cuda_runtime.h>
#include <cuda_fp16.h>
#include <math.h>
#include <stdint.h>

#define N_NODES 50000
#define E_RAW   400000
#define E_TOT   (E_RAW + N_NODES)   // 450000 with self loops
#define IN_DIM  128
#define H1      4
#define C1      64
#define F1      256                 // H1*C1
#define C2      64
#define OUT_DIM 3
#define NEG_SLOPE 0.2f
#define EPSV    1e-16f
#define NB_SCAN ((N_NODES + 255) / 256)   // 196 scan blocks

// ---------------- scratch (static device globals; no allocation) ----------------
__device__ __align__(16) __half g_h1h[N_NODES * F1];  // x @ W1 (fp16, gather only)
__device__ __align__(16) float  g_out1[N_NODES * F1]; // elu(agg1 + b1) -> layer-2 input
__device__ __align__(16) float  g_as1[N_NODES * H1];
__device__ __align__(16) float  g_ad1[N_NODES * H1];

__device__ __align__(16) __half g_h2h[N_NODES * C2];  // layer-2 linear (fp16, gather only)
__device__ float g_as2[N_NODES];
__device__ float g_ad2[N_NODES];

__device__ int g_cnt[N_NODES];       // in-degree (incl self loop)
__device__ int g_row[N_NODES];       // CSR row start
__device__ int g_fill[N_NODES];
__device__ int g_bsum[NB_SCAN];
__device__ int g_csr_src[E_TOT];     // src node per CSR slot
__device__ int g_is64;

// ---------------- helpers ----------------
__device__ __forceinline__ float eluf(float x) {
    return x > 0.f ? x : expm1f(x);
}

__device__ __forceinline__ void load_edge(const void* ei, int e, int& s, int& d) {
    if (e >= E_RAW) { s = d = e - E_RAW; return; }
    if (g_is64) {
        const long long* p = (const long long*)ei;
        s = (int)p[e];
        d = (int)p[E_RAW + e];
    } else {
        const int* p = (const int*)ei;
        s = p[e];
        d = p[E_RAW + e];
    }
}

// ---------------- edge index dtype detect ----------------
__global__ void detect_kernel(const unsigned int* __restrict__ ei32) {
    if (threadIdx.x == 0 && blockIdx.x == 0) {
        unsigned int ornz = 0;
        #pragma unroll
        for (int i = 0; i < 64; i++) ornz |= ei32[2 * i + 1];
        g_is64 = (ornz == 0u) ? 1 : 0;
    }
}

// ---------------- CSR build ----------------
__global__ void zero_kernel() {
    int n = blockIdx.x * blockDim.x + threadIdx.x;
    if (n < N_NODES) { g_cnt[n] = 0; g_fill[n] = 0; }
}

__global__ void count_kernel(const void* __restrict__ ei) {
    int e = blockIdx.x * blockDim.x + threadIdx.x;
    if (e >= E_TOT) return;
    int s, d; load_edge(ei, e, s, d);
    atomicAdd(&g_cnt[d], 1);
}

__global__ void scan1_kernel() {
    __shared__ int sm[256];
    int tid = threadIdx.x;
    int gid = blockIdx.x * 256 + tid;
    int v = (gid < N_NODES) ? g_cnt[gid] : 0;
    sm[tid] = v;
    __syncthreads();
    #pragma unroll
    for (int off = 1; off < 256; off <<= 1) {
        int t = (tid >= off) ? sm[tid - off] : 0;
        __syncthreads();
        sm[tid] += t;
        __syncthreads();
    }
    if (gid < N_NODES) g_row[gid] = sm[tid] - v;
    if (tid == 255) g_bsum[blockIdx.x] = sm[255];
}

// fused: each block computes its global offset from predecessor block sums, applies it
__global__ void scan23_kernel() {
    __shared__ int sred[256];
    int tid = threadIdx.x, bid = blockIdx.x;
    int v = 0;
    for (int i = tid; i < bid; i += 256) v += g_bsum[i];
    sred[tid] = v;
    __syncthreads();
    #pragma unroll
    for (int o = 128; o; o >>= 1) {
        if (tid < o) sred[tid] += sred[tid + o];
        __syncthreads();
    }
    int off = sred[0];
    int gid = bid * 256 + tid;
    if (gid < N_NODES) g_row[gid] += off;
}

__global__ void scatter_kernel(const void* __restrict__ ei) {
    int e = blockIdx.x * blockDim.x + threadIdx.x;
    if (e >= E_TOT) return;
    int s, d; load_edge(ei, e, s, d);
    int pos = g_row[d] + atomicAdd(&g_fill[d], 1);
    g_csr_src[pos] = s;
}

// ---------------- GEMM + fused attention scores, half output -------
// C[M,N] = A[M,K] @ B[K,N] (stored fp16); as_out[row,h] = sum_c C[row,h*64+c]*att[h*64+c]
// BM=128, BK=16, 256 threads (16x16), microtile 8 x TN. NH = BN/64 heads per block.
template<int BN, int TN, int NH>
__global__ __launch_bounds__(256, 2) void gemm_att_kernel(
    const float* __restrict__ A, const float* __restrict__ B, __half* __restrict__ C,
    const float* __restrict__ att_src, const float* __restrict__ att_dst,
    float* __restrict__ as_out, float* __restrict__ ad_out,
    int M, int K, int N, int HTOT)
{
    __shared__ float As[16][128];
    __shared__ float Bs[16][BN];
    const int tid = threadIdx.x;
    const int tx = tid & 15;
    const int ty = tid >> 4;
    const int by = blockIdx.y * 128, bx = blockIdx.x * BN;

    float acc[8][TN];
    #pragma unroll
    for (int m = 0; m < 8; m++)
        #pragma unroll
        for (int n = 0; n < TN; n++) acc[m][n] = 0.f;

    for (int k0 = 0; k0 < K; k0 += 16) {
        #pragma unroll
        for (int i = 0; i < 2; i++) {
            int idx = tid + i * 256;
            int r = idx >> 2, c4 = (idx & 3) * 4;
            int row = by + r;
            float4 v = make_float4(0.f, 0.f, 0.f, 0.f);
            if (row < M) v = *(const float4*)&A[(long)row * K + k0 + c4];
            As[c4 + 0][r] = v.x;
            As[c4 + 1][r] = v.y;
            As[c4 + 2][r] = v.z;
            As[c4 + 3][r] = v.w;
        }
        #pragma unroll
        for (int i = 0; i < BN / 64; i++) {
            int idx = tid + i * 256;
            int r = idx / (BN / 4), c4 = (idx % (BN / 4)) * 4;
            *(float4*)&Bs[r][c4] = *(const float4*)&B[(long)(k0 + r) * N + bx + c4];
        }
        __syncthreads();
        #pragma unroll
        for (int kk = 0; kk < 16; kk++) {
            float a[8], b[TN];
            #pragma unroll
            for (int m = 0; m < 8; m++) a[m] = As[kk][ty * 8 + m];
            #pragma unroll
            for (int n = 0; n < TN; n++) b[n] = Bs[kk][tx * TN + n];
            #pragma unroll
            for (int m = 0; m < 8; m++)
                #pragma unroll
                for (int n = 0; n < TN; n++)
                    acc[m][n] = fmaf(a[m], b[n], acc[m][n]);
        }
        __syncthreads();
    }

    // store C as fp16
    #pragma unroll
    for (int m = 0; m < 8; m++) {
        int row = by + ty * 8 + m;
        if (row < M) {
            __half2 pk[TN / 2];
            #pragma unroll
            for (int n = 0; n < TN; n += 2)
                pk[n / 2] = __floats2half2_rn(acc[m][n], acc[m][n + 1]);
            if (TN == 8)
                *(uint4*)&C[(long)row * N + bx + tx * TN] = *(uint4*)pk;
            else
                *(uint2*)&C[(long)row * N + bx + tx * TN] = *(uint2*)pk;
        }
    }

    // fused attention partials (fp32 accs; zero-padded rows give zero partials)
    float att_s[TN], att_d[TN];
    #pragma unroll
    for (int n = 0; n < TN; n++) {
        int col = bx + tx * TN + n;
        att_s[n] = att_src[col];
        att_d[n] = att_dst[col];
    }
    #pragma unroll
    for (int m = 0; m < 8; m++) {
        float s = 0.f, d = 0.f;
        #pragma unroll
        for (int n = 0; n < TN; n++) {
            s = fmaf(acc[m][n], att_s[n], s);
            d = fmaf(acc[m][n], att_d[n], d);
        }
        #pragma unroll
        for (int o = 4; o; o >>= 1) {
            s += __shfl_down_sync(0xffffffffu, s, o, 8);
            d += __shfl_down_sync(0xffffffffu, d, o, 8);
        }
        if (NH == 1) {
            s += __shfl_down_sync(0xffffffffu, s, 8, 16);
            d += __shfl_down_sync(0xffffffffu, d, 8, 16);
            if (tx == 0) {
                int row = by + ty * 8 + m;
                if (row < M) {
                    int head = bx / 64;
                    as_out[row * HTOT + head] = s;
                    ad_out[row * HTOT + head] = d;
                }
            }
        } else {
            if ((tx & 7) == 0) {
                int row = by + ty * 8 + m;
                if (row < M) {
                    int head = (bx + tx * TN) / 64;
                    as_out[row * HTOT + head] = s;
                    ad_out[row * HTOT + head] = d;
                }
            }
        }
    }
}

// ---------------- layer 1: single-pass fused softmax+agg via smem edge tiles --------
// one warp per dst node; lane owns cols [lane*8, lane*8+8) (16B fp16 per edge).
// out = (sum ex_i * h_i) / (sum ex_i)  -- normalization commutes with the sum.
__global__ __launch_bounds__(256) void agg1_kernel(const float* __restrict__ b1) {
    __shared__ float sv[8][32 * 4];
    __shared__ int   ss[8][32];
    int wi = threadIdx.x >> 5;
    int w = (blockIdx.x * blockDim.x + threadIdx.x) >> 5;
    int lane = threadIdx.x & 31;
    if (w >= N_NODES) return;
    int start = g_row[w];
    int end = start + g_cnt[w];

    float4 ad = *(const float4*)&g_ad1[w * H1];
    const int h = lane >> 3;
    const int cb = lane * 8;
    float4 den = make_float4(0.f, 0.f, 0.f, 0.f);
    float acc[8] = {};

    for (int t0 = start; t0 < end; t0 += 32) {
        // phase A: lane-parallel score+exp for this tile
        int i = t0 + lane;
        int s = 0;
        float4 v = make_float4(0.f, 0.f, 0.f, 0.f);
        if (i < end) {
            s = g_csr_src[i];
            float4 as = *(const float4*)&g_as1[s * H1];
            float tx_, ty_, tz_, tw_;
            tx_ = as.x + ad.x; ty_ = as.y + ad.y; tz_ = as.z + ad.z; tw_ = as.w + ad.w;
            v.x = __expf(tx_ > 0.f ? tx_ : NEG_SLOPE * tx_);
            v.y = __expf(ty_ > 0.f ? ty_ : NEG_SLOPE * ty_);
            v.z = __expf(tz_ > 0.f ? tz_ : NEG_SLOPE * tz_);
            v.w = __expf(tw_ > 0.f ? tw_ : NEG_SLOPE * tw_);
        }
        ss[wi][lane] = s;
        *(float4*)&sv[wi][lane * 4] = v;
        den.x += v.x; den.y += v.y; den.z += v.z; den.w += v.w;
        __syncwarp();

        // phase B: serial walk over tile, gather + accumulate (unroll x2)
        int m = end - t0; if (m > 32) m = 32;
        int j = 0;
        for (; j + 2 <= m; j += 2) {
            int s0 = ss[wi][j], s1 = ss[wi][j + 1];
            float e0 = sv[wi][j * 4 + h];
            float e1 = sv[wi][(j + 1) * 4 + h];
            uint4 r0 = *(const uint4*)&g_h1h[(long)s0 * F1 + cb];
            uint4 r1 = *(const uint4*)&g_h1h[(long)s1 * F1 + cb];
            const __half2* q0 = (const __half2*)&r0;
            const __half2* q1 = (const __half2*)&r1;
            #pragma unroll
            for (int k = 0; k < 4; k++) {
                float2 f0 = __half22float2(q0[k]);
                float2 f1 = __half22float2(q1[k]);
                acc[k * 2 + 0] = fmaf(e0, f0.x, acc[k * 2 + 0]);
                acc[k * 2 + 1] = fmaf(e0, f0.y, acc[k * 2 + 1]);
                acc[k * 2 + 0] = fmaf(e1, f1.x, acc[k * 2 + 0]);
                acc[k * 2 + 1] = fmaf(e1, f1.y, acc[k * 2 + 1]);
            }
        }
        if (j < m) {
            int s0 = ss[wi][j];
            float e0 = sv[wi][j * 4 + h];
            uint4 r0 = *(const uint4*)&g_h1h[(long)s0 * F1 + cb];
            const __half2* q0 = (const __half2*)&r0;
            #pragma unroll
            for (int k = 0; k < 4; k++) {
                float2 f0 = __half22float2(q0[k]);
                acc[k * 2 + 0] = fmaf(e0, f0.x, acc[k * 2 + 0]);
                acc[k * 2 + 1] = fmaf(e0, f0.y, acc[k * 2 + 1]);
            }
        }
        __syncwarp();
    }

    // reduce denominator across lanes, select this lane's head
    #pragma unroll
    for (int o = 16; o; o >>= 1) {
        den.x += __shfl_xor_sync(0xffffffffu, den.x, o);
        den.y += __shfl_xor_sync(0xffffffffu, den.y, o);
        den.z += __shfl_xor_sync(0xffffffffu, den.z, o);
        den.w += __shfl_xor_sync(0xffffffffu, den.w, o);
    }
    float denh = (h == 0) ? den.x : (h == 1) ? den.y : (h == 2) ? den.z : den.w;
    float inv = 1.f / (denh + EPSV);

    float4 bb0 = *(const float4*)&b1[cb];
    float4 bb1 = *(const float4*)&b1[cb + 4];
    float4 o0, o1;
    o0.x = eluf(fmaf(acc[0], inv, bb0.x)); o0.y = eluf(fmaf(acc[1], inv, bb0.y));
    o0.z = eluf(fmaf(acc[2], inv, bb0.z)); o0.w = eluf(fmaf(acc[3], inv, bb0.w));
    o1.x = eluf(fmaf(acc[4], inv, bb1.x)); o1.y = eluf(fmaf(acc[5], inv, bb1.y));
    o1.z = eluf(fmaf(acc[6], inv, bb1.z)); o1.w = eluf(fmaf(acc[7], inv, bb1.w));
    float4* op = (float4*)&g_out1[(long)w * F1 + cb];
    op[0] = o0;
    op[1] = o1;
}

// ---------------- layer 2: single-pass fused softmax+agg+bias+elu+head --------------
// one warp per dst node; lane owns cols [lane*2, lane*2+2)
__global__ __launch_bounds__(256) void agg2_kernel(const float* __restrict__ b2,
                                                   const float* __restrict__ Wout,
                                                   const float* __restrict__ bout,
                                                   float* __restrict__ out) {
    __shared__ float sv[8][32];
    __shared__ int   ss[8][32];
    int wi = threadIdx.x >> 5;
    int w = (blockIdx.x * blockDim.x + threadIdx.x) >> 5;
    int lane = threadIdx.x & 31;
    if (w >= N_NODES) return;
    int start = g_row[w];
    int end = start + g_cnt[w];

    float ad = g_ad2[w];
    float den = 0.f;
    const int c0 = lane * 2;
    float acc0 = 0.f, acc1 = 0.f;

    for (int t0 = start; t0 < end; t0 += 32) {
        int i = t0 + lane;
        int s = 0;
        float ex = 0.f;
        if (i < end) {
            s = g_csr_src[i];
            float v = g_as2[s] + ad;
            v = v > 0.f ? v : NEG_SLOPE * v;
            ex = __expf(v);
        }
        ss[wi][lane] = s;
        sv[wi][lane] = ex;
        den += ex;
        __syncwarp();

        int m = end - t0; if (m > 32) m = 32;
        int j = 0;
        for (; j + 2 <= m; j += 2) {
            int s0 = ss[wi][j], s1 = ss[wi][j + 1];
            float e0 = sv[wi][j], e1 = sv[wi][j + 1];
            __half2 h0 = *(const __half2*)&g_h2h[(long)s0 * C2 + c0];
            __half2 h1 = *(const __half2*)&g_h2h[(long)s1 * C2 + c0];
            float2 f0 = __half22float2(h0);
            float2 f1 = __half22float2(h1);
            acc0 = fmaf(e0, f0.x, acc0); acc1 = fmaf(e0, f0.y, acc1);
            acc0 = fmaf(e1, f1.x, acc0); acc1 = fmaf(e1, f1.y, acc1);
        }
        if (j < m) {
            int s0 = ss[wi][j];
            float e0 = sv[wi][j];
            __half2 h0 = *(const __half2*)&g_h2h[(long)s0 * C2 + c0];
            float2 f0 = __half22float2(h0);
            acc0 = fmaf(e0, f0.x, acc0); acc1 = fmaf(e0, f0.y, acc1);
        }
        __syncwarp();
    }

    #pragma unroll
    for (int o = 16; o; o >>= 1) den += __shfl_xor_sync(0xffffffffu, den, o);
    float inv = 1.f / (den + EPSV);

    float v0 = eluf(fmaf(acc0, inv, b2[c0]));
    float v1 = eluf(fmaf(acc1, inv, b2[c0 + 1]));
    float p0 = fmaf(v0, Wout[c0 * 3 + 0], v1 * Wout[(c0 + 1) * 3 + 0]);
    float p1 = fmaf(v0, Wout[c0 * 3 + 1], v1 * Wout[(c0 + 1) * 3 + 1]);
    float p2 = fmaf(v0, Wout[c0 * 3 + 2], v1 * Wout[(c0 + 1) * 3 + 2]);
    #pragma unroll
    for (int o = 16; o; o >>= 1) {
        p0 += __shfl_xor_sync(0xffffffffu, p0, o);
        p1 += __shfl_xor_sync(0xffffffffu, p1, o);
        p2 += __shfl_xor_sync(0xffffffffu, p2, o);
    }
    if (lane == 0) {
        out[w * 3 + 0] = p0 + bout[0];
        out[w * 3 + 1] = p1 + bout[1];
        out[w * 3 + 2] = p2 + bout[2];
    }
}

// ---------------- launch ----------------
extern "C" void kernel_launch(void* const* d_in, const int* in_sizes, int n_in,
                              void* d_out, int out_size) {
    const float* x        = (const float*)d_in[0];
    const void*  ei       = d_in[1];
    const float* W1       = (const float*)d_in[2];
    const float* att_src1 = (const float*)d_in[3];
    const float* att_dst1 = (const float*)d_in[4];
    const float* b1       = (const float*)d_in[5];
    const float* W2       = (const float*)d_in[6];
    const float* att_src2 = (const float*)d_in[7];
    const float* att_dst2 = (const float*)d_in[8];
    const float* b2       = (const float*)d_in[9];
    const float* Wout     = (const float*)d_in[10];
    const float* bout     = (const float*)d_in[11];
    float* out = (float*)d_out;

    __half *p_h1h, *p_h2h;
    float *p_out1, *p_as1, *p_ad1, *p_as2, *p_ad2;
    cudaGetSymbolAddress((void**)&p_h1h,  g_h1h);
    cudaGetSymbolAddress((void**)&p_h2h,  g_h2h);
    cudaGetSymbolAddress((void**)&p_out1, g_out1);
    cudaGetSymbolAddress((void**)&p_as1,  g_as1);
    cudaGetSymbolAddress((void**)&p_ad1,  g_ad1);
    cudaGetSymbolAddress((void**)&p_as2,  g_as2);
    cudaGetSymbolAddress((void**)&p_ad2,  g_ad2);

    const int T = 256;
    const int EB = (E_TOT + T - 1) / T;

    // CSR build
    detect_kernel<<<1, 32>>>((const unsigned int*)ei);
    zero_kernel<<<NB_SCAN, T>>>();
    count_kernel<<<EB, T>>>(ei);
    scan1_kernel<<<NB_SCAN, 256>>>();
    scan23_kernel<<<NB_SCAN, 256>>>();
    scatter_kernel<<<EB, T>>>(ei);

    // layer 1: GEMM (+fused attscore, fp16 C), then aggregation
    {
        dim3 grid(F1 / 128, (N_NODES + 127) / 128);
        gemm_att_kernel<128, 8, 2><<<grid, 256>>>(x, W1, p_h1h, att_src1, att_dst1,
                                                  p_as1, p_ad1, N_NODES, IN_DIM, F1, H1);
    }
    agg1_kernel<<<(N_NODES * 32 + T - 1) / T, T>>>(b1);

    // layer 2
    {
        dim3 grid(C2 / 64, (N_NODES + 127) / 128);
        gemm_att_kernel<64, 4, 1><<<grid, 256>>>(p_out1, W2, p_h2h, att_src2, att_dst2,
                                                 p_as2, p_ad2, N_NODES, F1, C2, 1);
    }
    agg2_kernel<<<(N_NODES * 32 + T - 1) / T, T>>>(b2, Wout, bout, out);
}